// round 15
// baseline (speedup 1.0000x reference)
#include <cuda_runtime.h>
#include <cuda_fp16.h>
#include <cstdint>
#include <cstddef>

// ---------------------------------------------------------------------------
// Problem constants
// ---------------------------------------------------------------------------
#define Dm    512
#define Bn    8
#define Hh    64
#define Ww    64
#define Nn    (Hh*Ww)      // 4096
#define Qq    200
#define C2    256
#define NH    8
#define NH2   4
#define HD    64
#define L1    256
#define L2    1024
#define M1    (Bn*L1)      // 2048
#define M2    (Bn*L2)      // 8192
#define K1    (Dm*16)      // 8192
#define K2    (Dm*4)       // 2048
#define MQ    (Qq*Bn)      // 1600
#define NBH   32
#define ROWS1 (NBH*Qq)     // 6400
#define LNROWS (2*(M1+M2)) // 20480

// ---------------------------------------------------------------------------
// scratch pools
// ---------------------------------------------------------------------------
constexpr size_t H_W11T = 0;
constexpr size_t H_W12T = H_W11T + 512u*8192u;
constexpr size_t H_W21T = H_W12T + 512u*8192u;
constexpr size_t H_W22T = H_W21T + 512u*2048u;
constexpr size_t H_QWR  = H_W22T + 512u*2048u;
constexpr size_t H_PWR  = H_QWR  + 512u*512u;
constexpr size_t H_KW1R = H_PWR  + 512u*512u;
constexpr size_t H_VW1R = H_KW1R + 256u*512u;
constexpr size_t H_KW2R = H_VW1R + 256u*512u;
constexpr size_t H_VW2R = H_KW2R + 256u*512u;
constexpr size_t H_QR   = H_VW2R + 256u*512u;
constexpr size_t H_KEYR = H_QR   + (size_t)MQ*512u;
constexpr size_t H_VALR = H_KEYR + (size_t)Bn*Nn*512u;
constexpr size_t H_LN1K = H_VALR + (size_t)Bn*Nn*512u;
constexpr size_t H_LN1V = H_LN1K + (size_t)M1*512u;
constexpr size_t H_LN2K = H_LN1V + (size_t)M1*512u;
constexpr size_t H_LN2V = H_LN2K + (size_t)M2*512u;
constexpr size_t H_PQ   = H_LN2V + (size_t)M2*512u;
constexpr size_t H_KB1  = H_PQ   + (size_t)MQ*512u;
constexpr size_t H_KB2  = H_KB1  + (size_t)M1*256u;
constexpr size_t H_VS1  = H_KB2  + (size_t)M2*256u;
constexpr size_t H_VS2  = H_VS1  + (size_t)M1*256u;
constexpr size_t H_P1   = H_VS2  + (size_t)M2*256u;
constexpr size_t H_P2   = H_P1   + (size_t)ROWS1*L1;
constexpr size_t H_X    = H_P2   + (size_t)ROWS1*L2;
constexpr size_t H_TOTAL = H_X   + (size_t)MQ*512u;

__device__ __align__(16) __half g_h[H_TOTAL];

constexpr size_t S_C1K  = 0;
constexpr size_t S_C1KB = S_C1K  + (size_t)M1*512u;
constexpr size_t S_C1V  = S_C1KB + (size_t)M1*512u;
constexpr size_t S_C1VB = S_C1V  + (size_t)M1*512u;
constexpr size_t S_C2K  = S_C1VB + (size_t)M1*512u;
constexpr size_t S_C2V  = S_C2K  + (size_t)M2*512u;
constexpr size_t S_VB1  = S_C2V  + (size_t)M2*512u;
constexpr size_t S_VB2  = S_VB1  + (size_t)M1*256u;
constexpr size_t S_S1   = S_VB2  + (size_t)M2*256u;
constexpr size_t S_S2   = S_S1   + (size_t)ROWS1*L1;
constexpr size_t S_INV1 = S_S2   + (size_t)ROWS1*L2;
constexpr size_t S_INV2 = S_INV1 + ROWS1;
constexpr size_t S_TOTAL = S_INV2 + ROWS1;

__device__ __align__(16) float g_f[S_TOTAL];

// ---------------------------------------------------------------------------
// helpers
// ---------------------------------------------------------------------------
__device__ __forceinline__ uint32_t smem_u32(const void* p) {
    uint32_t a;
    asm("{ .reg .u64 t; cvta.to.shared.u64 t, %1; cvt.u32.u64 %0, t; }" : "=r"(a) : "l"(p));
    return a;
}

#define MMA_F16(c, a, b) \
    asm volatile("mma.sync.aligned.m16n8k16.row.col.f32.f16.f16.f32 " \
        "{%0,%1,%2,%3}, {%4,%5,%6,%7}, {%8,%9}, {%0,%1,%2,%3};" \
        : "+f"((c)[0]), "+f"((c)[1]), "+f"((c)[2]), "+f"((c)[3]) \
        : "r"((a)[0]), "r"((a)[1]), "r"((a)[2]), "r"((a)[3]), \
          "r"((b)[0]), "r"((b)[1]))

#define LDSM4(r0, r1, r2, r3, addr) \
    asm volatile("ldmatrix.sync.aligned.m8n8.x4.shared.b16 {%0,%1,%2,%3}, [%4];" \
        : "=r"(r0), "=r"(r1), "=r"(r2), "=r"(r3) : "r"(addr))

#define LDSM4T(r0, r1, r2, r3, addr) \
    asm volatile("ldmatrix.sync.aligned.m8n8.x4.trans.shared.b16 {%0,%1,%2,%3}, [%4];" \
        : "=r"(r0), "=r"(r1), "=r"(r2), "=r"(r3) : "r"(addr))

__global__ void k_nop() {}

// ---------------------------------------------------------------------------
// Conv-weight transpose -> fp16
// ---------------------------------------------------------------------------
struct TwP {
    const float* src[4];
    __half* dst[4];
};
__global__ void __launch_bounds__(256) k_tw_conv(TwP tp) {
    __shared__ float smem[512 * 17];
    int seg = blockIdx.y;
    int co = blockIdx.x;
    int P = (seg < 2) ? 16 : 4;
    int pad = P + 1;
    int n = 512 * P;
    const float* s = tp.src[seg] + (size_t)co * n;
    __half* d = tp.dst[seg] + (size_t)co * n;
    for (int i = threadIdx.x; i < n; i += 256) {
        int ci = i / P, p = i % P;
        smem[ci * pad + p] = s[i];
    }
    __syncthreads();
    for (int j = threadIdx.x; j < n; j += 256) {
        int p = j >> 9, ci = j & 511;
        d[j] = __float2half_rn(smem[ci * pad + p]);
    }
}

// ---------------------------------------------------------------------------
// float4 -> half4 convert, flattened 1-D grid
// ---------------------------------------------------------------------------
struct PrepH {
    const float* src[9];
    __half* dst[9];
    int start[10];
};
__global__ void k_prep(PrepH pa) {
    int blk = blockIdx.x;
    int seg = 0;
    #pragma unroll
    for (int i = 1; i < 9; i++)
        if (blk >= pa.start[i]) seg = i;
    long long i = (long long)(blk - pa.start[seg]) * 256 + threadIdx.x;
    float4 v = ((const float4*)pa.src[seg])[i];
    __half2 h0 = __floats2half2_rn(v.x, v.y);
    __half2 h1 = __floats2half2_rn(v.z, v.w);
    uint2 o;
    o.x = *reinterpret_cast<uint32_t*>(&h0);
    o.y = *reinterpret_cast<uint32_t*>(&h1);
    ((uint2*)pa.dst[seg])[i] = o;
}

// ---------------------------------------------------------------------------
// FP16 GEMM, multi-segment (up to 7).  2-stage double buffer, ldmatrix.
// lda/ldb allow split-K segments (B row stride != segment K).
// ---------------------------------------------------------------------------
struct GSeg {
    const __half* A;
    const __half* B;
    float* C;
    __half* Ch;
    const float* bias;
    float scale;
    int M, N, K, lda, ldb, mode, start, tilesX;
};
struct GemmP {
    GSeg s[7];
    int nseg;
};

#define PITCHH 72
#define PLANEB (128 * PITCHH * 2)       // 18432
#define STAGEB (2 * PLANEB)             // 36864
#define GSMEM_BYTES (2 * STAGEB)        // 73728

__global__ void __launch_bounds__(256, 2) k_gemm(GemmP g) {
    extern __shared__ char smc[];
    int si = 0;
    #pragma unroll
    for (int i = 1; i < 7; i++)
        if (i < g.nseg && (int)blockIdx.x >= g.s[i].start) si = i;
    const __half* A = g.s[si].A;
    const __half* B = g.s[si].B;
    float* C = g.s[si].C;
    __half* Ch = g.s[si].Ch;
    const float* bias = g.s[si].bias;
    float scale = g.s[si].scale;
    int M = g.s[si].M, N = g.s[si].N, K = g.s[si].K, mode = g.s[si].mode;
    int lda = g.s[si].lda, ldb = g.s[si].ldb;
    int t0 = blockIdx.x - g.s[si].start;
    int colBase = (t0 % g.s[si].tilesX) * 128;
    int rowBase = (t0 / g.s[si].tilesX) * 128;
    int tid = threadIdx.x, wid = tid >> 5, lane = tid & 31;
    int wm = wid & 1, wn = wid >> 1;
    uint32_t sb = smem_u32(smc);

    auto issue = [&](int stage, int kb) {
        uint32_t sbase = sb + stage * STAGEB;
        #pragma unroll
        for (int t = 0; t < 4; t++) {
            int cid = tid + t * 256;
            int r = cid >> 3, ch = cid & 7;
            int grow = rowBase + r;
            const __half* src;
            int sz = 16;
            if (mode == 0) {
                if (grow >= M) { sz = 0; grow = 0; }
                src = A + (size_t)grow * lda + kb + ch * 8;
            } else if (mode == 1) {
                int b = grow >> 8, rem = grow & 255;
                int oy = rem >> 4, ox = rem & 15;
                int p = kb >> 9;
                int y = oy * 4 + (p >> 2), x = ox * 4 + (p & 3);
                src = A + (((size_t)((b << 12) + (y << 6) + x)) << 9) + (kb & 511) + ch * 8;
            } else {
                int b = grow >> 10, oy = (grow >> 5) & 31, ox = grow & 31;
                int p = kb >> 9;
                int y = oy * 2 + (p >> 1), x = ox * 2 + (p & 1);
                src = A + (((size_t)((b << 12) + (y << 6) + x)) << 9) + (kb & 511) + ch * 8;
            }
            uint32_t sa = sbase + (uint32_t)(r * (PITCHH * 2)) + ch * 16;
            asm volatile("cp.async.cg.shared.global [%0], [%1], 16, %2;"
                         :: "r"(sa), "l"(src), "r"(sz) : "memory");
        }
        #pragma unroll
        for (int t = 0; t < 4; t++) {
            int cid = tid + t * 256;
            int r = cid >> 3, ch = cid & 7;
            const __half* src = B + (size_t)(colBase + r) * ldb + kb + ch * 8;
            uint32_t sa = sbase + PLANEB + (uint32_t)(r * (PITCHH * 2)) + ch * 16;
            asm volatile("cp.async.cg.shared.global [%0], [%1], 16, 16;"
                         :: "r"(sa), "l"(src) : "memory");
        }
        asm volatile("cp.async.commit_group;" ::: "memory");
    };

    float acc[4][4][4];
    #pragma unroll
    for (int a = 0; a < 4; a++)
        #pragma unroll
        for (int b = 0; b < 4; b++)
            #pragma unroll
            for (int c = 0; c < 4; c++) acc[a][b][c] = 0.f;

    uint32_t aoff[4], boff[2];
    {
        int rIn = (lane & 7) + (((lane >> 3) & 1) << 3);
        int kA = (lane >> 4) << 3;
        #pragma unroll
        for (int mt = 0; mt < 4; mt++)
            aoff[mt] = (uint32_t)(((wm * 64 + mt * 16 + rIn) * PITCHH + kA) * 2);
        int rB = ((lane >> 4) << 3) + (lane & 7);
        int kB = ((lane >> 3) & 1) << 3;
        #pragma unroll
        for (int bp = 0; bp < 2; bp++)
            boff[bp] = (uint32_t)(PLANEB + ((wn * 32 + bp * 16 + rB) * PITCHH + kB) * 2);
    }

    int niter = K >> 6;
    issue(0, 0);
    int r4 = lane >> 2, c4 = lane & 3;

    for (int it = 0; it < niter; it++) {
        if (it + 1 < niter) {
            issue((it + 1) & 1, (it + 1) << 6);
            asm volatile("cp.async.wait_group 1;" ::: "memory");
        } else {
            asm volatile("cp.async.wait_group 0;" ::: "memory");
        }
        __syncthreads();
        uint32_t sbase = sb + (it & 1) * STAGEB;

        #pragma unroll
        for (int kk = 0; kk < 64; kk += 16) {
            uint32_t af[4][4], bf_[4][2];
            uint32_t kb2 = kk * 2;
            #pragma unroll
            for (int mt = 0; mt < 4; mt++)
                LDSM4(af[mt][0], af[mt][1], af[mt][2], af[mt][3], sbase + aoff[mt] + kb2);
            LDSM4(bf_[0][0], bf_[0][1], bf_[1][0], bf_[1][1], sbase + boff[0] + kb2);
            LDSM4(bf_[2][0], bf_[2][1], bf_[3][0], bf_[3][1], sbase + boff[1] + kb2);
            #pragma unroll
            for (int mt = 0; mt < 4; mt++)
                #pragma unroll
                for (int nt = 0; nt < 4; nt++)
                    MMA_F16(acc[mt][nt], af[mt], bf_[nt]);
        }
        __syncthreads();
    }

    #pragma unroll
    for (int mt = 0; mt < 4; mt++) {
        #pragma unroll
        for (int nt = 0; nt < 4; nt++) {
            int m0 = rowBase + wm * 64 + mt * 16 + r4;
            int n0 = colBase + wn * 32 + nt * 8 + 2 * c4;
            if (Ch) {
                if (m0 < M) {
                    __half2 hv = __floats2half2_rn(acc[mt][nt][0] * scale, acc[mt][nt][1] * scale);
                    *(__half2*)(Ch + (size_t)m0 * N + n0) = hv;
                }
                if (m0 + 8 < M) {
                    __half2 hv = __floats2half2_rn(acc[mt][nt][2] * scale, acc[mt][nt][3] * scale);
                    *(__half2*)(Ch + (size_t)(m0 + 8) * N + n0) = hv;
                }
            } else {
                float bx = 0.f, by = 0.f;
                if (bias) { bx = bias[n0]; by = bias[n0 + 1]; }
                if (m0 < M) {
                    float2 v = make_float2(acc[mt][nt][0] + bx, acc[mt][nt][1] + by);
                    *(float2*)(C + (size_t)m0 * N + n0) = v;
                }
                if (m0 + 8 < M) {
                    float2 v = make_float2(acc[mt][nt][2] + bx, acc[mt][nt][3] + by);
                    *(float2*)(C + (size_t)(m0 + 8) * N + n0) = v;
                }
            }
        }
    }
}

// ---------------------------------------------------------------------------
// bias + LayerNorm(512) + relu6 -> fp16.  Warp-per-row.  Optional second
// input (split-K partial sums) added on load.
// ---------------------------------------------------------------------------
struct LnP {
    const float* x[4];
    const float* x2[4];
    const float* cb[4];
    const float* g[4];
    const float* b[4];
    __half* o[4];
};
__global__ void __launch_bounds__(256) k_biasln(LnP p) {
    int gr = blockIdx.x * 8 + (threadIdx.x >> 5);
    int lane = threadIdx.x & 31;
    if (gr >= LNROWS) return;
    int seg, row;
    if (gr < M1) { seg = 0; row = gr; }
    else if (gr < 2 * M1) { seg = 1; row = gr - M1; }
    else if (gr < 2 * M1 + M2) { seg = 2; row = gr - 2 * M1; }
    else { seg = 3; row = gr - 2 * M1 - M2; }
    const float* xr = p.x[seg] + (size_t)row * 512;
    const float* x2r = p.x2[seg] ? p.x2[seg] + (size_t)row * 512 : nullptr;
    const float* cb = p.cb[seg];
    const float* gg = p.g[seg];
    const float* bb = p.b[seg];
    __half* orow = p.o[seg] + (size_t)row * 512;

    float4 v[4];
    float s = 0.f;
    #pragma unroll
    for (int i = 0; i < 4; i++) {
        int off = lane * 4 + i * 128;
        float4 xv = *(const float4*)(xr + off);
        float4 cv = *(const float4*)(cb + off);
        v[i] = make_float4(xv.x + cv.x, xv.y + cv.y, xv.z + cv.z, xv.w + cv.w);
        if (x2r) {
            float4 x2v = *(const float4*)(x2r + off);
            v[i].x += x2v.x; v[i].y += x2v.y; v[i].z += x2v.z; v[i].w += x2v.w;
        }
        s += v[i].x + v[i].y + v[i].z + v[i].w;
    }
    #pragma unroll
    for (int off = 16; off; off >>= 1) s += __shfl_xor_sync(0xffffffffu, s, off);
    float mean = s * (1.f / 512.f);
    float s2 = 0.f;
    #pragma unroll
    for (int i = 0; i < 4; i++) {
        v[i].x -= mean; v[i].y -= mean; v[i].z -= mean; v[i].w -= mean;
        s2 += v[i].x * v[i].x + v[i].y * v[i].y + v[i].z * v[i].z + v[i].w * v[i].w;
    }
    #pragma unroll
    for (int off = 16; off; off >>= 1) s2 += __shfl_xor_sync(0xffffffffu, s2, off);
    float inv = rsqrtf(s2 * (1.f / 512.f) + 1e-5f);
    #pragma unroll
    for (int i = 0; i < 4; i++) {
        int off = lane * 4 + i * 128;
        float4 gv = *(const float4*)(gg + off);
        float4 bv = *(const float4*)(bb + off);
        float y0 = fminf(fmaxf(v[i].x * inv * gv.x + bv.x, 0.f), 6.f);
        float y1 = fminf(fmaxf(v[i].y * inv * gv.y + bv.y, 0.f), 6.f);
        float y2 = fminf(fmaxf(v[i].z * inv * gv.z + bv.z, 0.f), 6.f);
        float y3 = fminf(fmaxf(v[i].w * inv * gv.w + bv.w, 0.f), 6.f);
        __half2 h0 = __floats2half2_rn(y0, y1);
        __half2 h1 = __floats2half2_rn(y2, y3);
        uint2 o;
        o.x = *reinterpret_cast<uint32_t*>(&h0);
        o.y = *reinterpret_cast<uint32_t*>(&h1);
        *(uint2*)(orow + off) = o;
    }
}

// ---------------------------------------------------------------------------
// depthwise 3x3 (pad 1) + bias + residual -> fp16, channel-pair vectorized
// ---------------------------------------------------------------------------
struct DwP {
    const float* v[2];
    __half* vs[2];
    const float* lw[2];
    const float* lb[2];
};
__global__ void k_dwadd(DwP p) {
    long long idx = (long long)blockIdx.x * 256 + threadIdx.x;
    const long long tot1 = (long long)M1 * 128;
    const long long tot2 = (long long)M2 * 128;
    int br;
    long long li;
    if (idx < tot1) { br = 0; li = idx; }
    else { idx -= tot1; if (idx >= tot2) return; br = 1; li = idx; }
    int hh = br ? 32 : 16, ww = hh;
    int L = hh * ww;
    int c = (int)(li & 127) << 1;
    int l = (int)((li >> 7) % L);
    int b = (int)(li / ((long long)L << 7));
    int y = l / ww, x = l % ww;
    const float* v = p.v[br];
    const float* lw = p.lw[br];
    float2 acc = make_float2(p.lb[br][c], p.lb[br][c + 1]);
    #pragma unroll
    for (int dy = 0; dy < 3; dy++) {
        int yy = y + dy - 1;
        if ((unsigned)yy >= (unsigned)hh) continue;
        #pragma unroll
        for (int dx = 0; dx < 3; dx++) {
            int xx = x + dx - 1;
            if ((unsigned)xx >= (unsigned)ww) continue;
            float2 vv = *(const float2*)&v[(((long long)b * L + yy * ww + xx) << 8) + c];
            int t = dy * 3 + dx;
            acc.x += vv.x * lw[c * 9 + t];
            acc.y += vv.y * lw[(c + 1) * 9 + t];
        }
    }
    float2 v0 = *(const float2*)&v[li << 1];
    *(__half2*)&p.vs[br][li << 1] = __floats2half2_rn(v0.x + acc.x, v0.y + acc.y);
}

// ---------------------------------------------------------------------------
// Attention S = Q @ K^T.  128x128 fp16 MMA, K=64, ldmatrix loads.
// ---------------------------------------------------------------------------
struct AttnSP {
    const __half* Qh;
    const __half* Kh[2];
    float* S[2];
};
#define ASMEM_BYTES STAGEB

__global__ void __launch_bounds__(256) k_attn_s(AttnSP p) {
    extern __shared__ char smc[];
    int xh = blockIdx.x, hg = blockIdx.y, b = blockIdx.z;
    int branch = hg >> 2, h = hg & 3;
    int L = branch ? L2 : L1;
    int lt = xh >> 1, mt_ = xh & 1;
    if (lt >= (L >> 7)) return;
    int rowBase = mt_ * 128, colBase = lt * 128;
    int tid = threadIdx.x, wid = tid >> 5, lane = tid & 31;
    int wm = wid & 1, wn = wid >> 1;
    uint32_t sb = smem_u32(smc);
    const __half* Qh = p.Qh;
    const __half* Kh = p.Kh[branch];

    #pragma unroll
    for (int t = 0; t < 4; t++) {
        int cid = tid + t * 256;
        int r = cid >> 3, ch = cid & 7;
        int q = rowBase + r;
        int sz = (q < Qq) ? 16 : 0;
        int qc = sz ? q : 0;
        const __half* src = Qh + ((size_t)(b * Qq + qc) * NH + hg) * 64 + ch * 8;
        uint32_t sa = sb + (uint32_t)(r * (PITCHH * 2)) + ch * 16;
        asm volatile("cp.async.cg.shared.global [%0], [%1], 16, %2;"
                     :: "r"(sa), "l"(src), "r"(sz) : "memory");
        int l = colBase + r;
        const __half* srcB = Kh + ((size_t)(b * L + l)) * 256 + h * 64 + ch * 8;
        uint32_t sab = sb + PLANEB + (uint32_t)(r * (PITCHH * 2)) + ch * 16;
        asm volatile("cp.async.cg.shared.global [%0], [%1], 16, 16;"
                     :: "r"(sab), "l"(srcB) : "memory");
    }
    asm volatile("cp.async.commit_group;" ::: "memory");
    asm volatile("cp.async.wait_group 0;" ::: "memory");
    __syncthreads();

    float acc[4][4][4];
    #pragma unroll
    for (int a = 0; a < 4; a++)
        #pragma unroll
        for (int bb = 0; bb < 4; bb++)
            #pragma unroll
            for (int c = 0; c < 4; c++) acc[a][bb][c] = 0.f;

    uint32_t aoff[4], boff[2];
    {
        int rIn = (lane & 7) + (((lane >> 3) & 1) << 3);
        int kA = (lane >> 4) << 3;
        #pragma unroll
        for (int mt = 0; mt < 4; mt++)
            aoff[mt] = (uint32_t)(((wm * 64 + mt * 16 + rIn) * PITCHH + kA) * 2);
        int rB = ((lane >> 4) << 3) + (lane & 7);
        int kB = ((lane >> 3) & 1) << 3;
        #pragma unroll
        for (int bp = 0; bp < 2; bp++)
            boff[bp] = (uint32_t)(PLANEB + ((wn * 32 + bp * 16 + rB) * PITCHH + kB) * 2);
    }
    int r4 = lane >> 2, c4 = lane & 3;

    #pragma unroll
    for (int kk = 0; kk < 64; kk += 16) {
        uint32_t af[4][4], bf_[4][2];
        uint32_t kb2 = kk * 2;
        #pragma unroll
        for (int mt = 0; mt < 4; mt++)
            LDSM4(af[mt][0], af[mt][1], af[mt][2], af[mt][3], sb + aoff[mt] + kb2);
        LDSM4(bf_[0][0], bf_[0][1], bf_[1][0], bf_[1][1], sb + boff[0] + kb2);
        LDSM4(bf_[2][0], bf_[2][1], bf_[3][0], bf_[3][1], sb + boff[1] + kb2);
        #pragma unroll
        for (int mt = 0; mt < 4; mt++)
            #pragma unroll
            for (int nt = 0; nt < 4; nt++)
                MMA_F16(acc[mt][nt], af[mt], bf_[nt]);
    }

    float* Sb = p.S[branch] + (size_t)((b * 4 + h) * Qq) * L;
    #pragma unroll
    for (int mt = 0; mt < 4; mt++) {
        #pragma unroll
        for (int nt = 0; nt < 4; nt++) {
            int m0 = rowBase + wm * 64 + mt * 16 + r4;
            int n0 = colBase + wn * 32 + nt * 8 + 2 * c4;
            if (m0 < Qq)
                *(float2*)(Sb + (size_t)m0 * L + n0) =
                    make_float2(acc[mt][nt][0], acc[mt][nt][1]);
            if (m0 + 8 < Qq)
                *(float2*)(Sb + (size_t)(m0 + 8) * L + n0) =
                    make_float2(acc[mt][nt][2], acc[mt][nt][3]);
        }
    }
}

// ---------------------------------------------------------------------------
// softmax: one warp per row, float4 vectorized
// ---------------------------------------------------------------------------
struct SmP {
    const float* S[2];
    __half* P[2];
    float* inv[2];
};
__global__ void __launch_bounds__(256) k_softmax(SmP p) {
    int r = blockIdx.x * 8 + (threadIdx.x >> 5);
    int lane = threadIdx.x & 31;
    int branch = (r >= ROWS1) ? 1 : 0;
    int local = r - branch * ROWS1;
    int L = branch ? L2 : L1;
    const float* S = p.S[branch] + (size_t)local * L;
    __half* P = p.P[branch] + (size_t)local * L;
    int n4 = L >> 7;
    float m = -1e30f;
    for (int i = 0; i < n4; i++) {
        float4 v = *(const float4*)(S + (i * 128 + lane * 4));
        m = fmaxf(m, fmaxf(fmaxf(v.x, v.y), fmaxf(v.z, v.w)));
    }
    #pragma unroll
    for (int off = 16; off; off >>= 1) m = fmaxf(m, __shfl_xor_sync(0xffffffffu, m, off));
    float s = 0.f;
    for (int i = 0; i < n4; i++) {
        int off = i * 128 + lane * 4;
        float4 v = *(const float4*)(S + off);
        float e0 = __expf(v.x - m), e1 = __expf(v.y - m);
        float e2 = __expf(v.z - m), e3 = __expf(v.w - m);
        s += e0 + e1 + e2 + e3;
        __half2 h0 = __floats2half2_rn(e0, e1);
        __half2 h1 = __floats2half2_rn(e2, e3);
        uint2 o;
        o.x = *reinterpret_cast<uint32_t*>(&h0);
        o.y = *reinterpret_cast<uint32_t*>(&h1);
        *(uint2*)(P + off) = o;
    }
    #pragma unroll
    for (int off = 16; off; off >>= 1) s += __shfl_xor_sync(0xffffffffu, s, off);
    if (lane == 0) p.inv[branch][local] = 1.f / s;
}

// ---------------------------------------------------------------------------
// Attention O = P @ V, N=64, K=L; 2-stage double buffer; V via ldmatrix.trans.
// ---------------------------------------------------------------------------
struct AttnOP {
    const __half* P[2];
    const __half* VS[2];
    const float* inv[2];
    __half* xbuf;
};
__global__ void __launch_bounds__(256, 2) k_attn_o(AttnOP p) {
    extern __shared__ char smc[];
    int mt_ = blockIdx.x, hg = blockIdx.y, b = blockIdx.z;
    int branch = hg >> 2, h = hg & 3;
    int L = branch ? L2 : L1;
    int rowBase = mt_ * 128;
    int tid = threadIdx.x, wid = tid >> 5, lane = tid & 31;
    int wm = wid & 1, wn = wid >> 1;
    uint32_t sb = smem_u32(smc);
    const __half* Pm = p.P[branch] + (size_t)((b * 4 + h) * Qq) * L;
    const __half* VS = p.VS[branch];
    const float* inv = p.inv[branch] + (b * 4 + h) * Qq;

    auto issue = [&](int stage, int kb) {
        uint32_t sbase = sb + stage * STAGEB;
        #pragma unroll
        for (int t = 0; t < 4; t++) {
            int cid = tid + t * 256;
            int r = cid >> 3, ch = cid & 7;
            int q = rowBase + r;
            int sz = (q < Qq) ? 16 : 0;
            int qc = sz ? q : 0;
            const __half* src = Pm + (size_t)qc * L + kb + ch * 8;
            uint32_t sa = sbase + (uint32_t)(r * (PITCHH * 2)) + ch * 16;
            asm volatile("cp.async.cg.shared.global [%0], [%1], 16, %2;"
                         :: "r"(sa), "l"(src), "r"(sz) : "memory");
            int szb = (r < 64) ? 16 : 0;
            int rc = szb ? r : 0;
            const __half* srcB = VS + ((size_t)(b * L + kb + rc)) * 256 + h * 64 + ch * 8;
            uint32_t sab = sbase + PLANEB + (uint32_t)(r * (PITCHH * 2)) + ch * 16;
            asm volatile("cp.async.cg.shared.global [%0], [%1], 16, %2;"
                         :: "r"(sab), "l"(srcB), "r"(szb) : "memory");
        }
        asm volatile("cp.async.commit_group;" ::: "memory");
    };

    float acc[4][4][4];
    #pragma unroll
    for (int a = 0; a < 4; a++)
        #pragma unroll
        for (int bb = 0; bb < 4; bb++)
            #pragma unroll
            for (int c = 0; c < 4; c++) acc[a][bb][c] = 0.f;

    uint32_t aoff[4], boffT[2];
    {
        int rIn = (lane & 7) + (((lane >> 3) & 1) << 3);
        int kA = (lane >> 4) << 3;
        #pragma unroll
        for (int mt = 0; mt < 4; mt++)
            aoff[mt] = (uint32_t)(((wm * 64 + mt * 16 + rIn) * PITCHH + kA) * 2);
        int rT = (lane & 7) + (((lane >> 3) & 1) << 3);
        int nT0 = (lane >> 4) << 3;
        #pragma unroll
        for (int bp = 0; bp < 2; bp++)
            boffT[bp] = (uint32_t)(PLANEB + (rT * PITCHH + wn * 32 + bp * 16 + nT0) * 2);
    }

    int niter = L >> 6;
    issue(0, 0);
    int r4 = lane >> 2, c4 = lane & 3;

    for (int it = 0; it < niter; it++) {
        if (it + 1 < niter) {
            issue((it + 1) & 1, (it + 1) << 6);
            asm volatile("cp.async.wait_group 1;" ::: "memory");
        } else {
            asm volatile("cp.async.wait_group 0;" ::: "memory");
        }
        __syncthreads();
        uint32_t sbase = sb + (it & 1) * STAGEB;

        #pragma unroll
        for (int kk = 0; kk < 64; kk += 16) {
            uint32_t af[4][4], bf_[4][2];
            uint32_t kb2 = kk * 2;
            uint32_t krow = (uint32_t)kk * (PITCHH * 2);
            #pragma unroll
            for (int mt = 0; mt < 4; mt++)
                LDSM4(af[mt][0], af[mt][1], af[mt][2], af[mt][3], sbase + aoff[mt] + kb2);
            LDSM4T(bf_[0][0], bf_[0][1], bf_[1][0], bf_[1][1], sbase + boffT[0] + krow);
            LDSM4T(bf_[2][0], bf_[2][1], bf_[3][0], bf_[3][1], sbase + boffT[1] + krow);
            #pragma unroll
            for (int mt = 0; mt < 4; mt++)
                #pragma unroll
                for (int nt = 0; nt < 4; nt++)
                    MMA_F16(acc[mt][nt], af[mt], bf_[nt]);
        }
        __syncthreads();
    }

    __half* xb = p.xbuf;
    #pragma unroll
    for (int mt = 0; mt < 4; mt++) {
        int m0 = rowBase + wm * 64 + mt * 16 + r4;
        float iv0 = (m0 < Qq) ? inv[m0] : 0.f;
        float iv1 = (m0 + 8 < Qq) ? inv[m0 + 8] : 0.f;
        #pragma unroll
        for (int nt = 0; nt < 4; nt++) {
            int n0 = wn * 32 + nt * 8 + 2 * c4;
            if (n0 < 64) {
                if (m0 < Qq) {
                    int f = (((b * Qq + m0) << 2) + h) * 64 + n0;
                    int q2 = f >> 11, rem = f & 2047, b2 = rem >> 8, c2 = rem & 255;
                    __half2 hv = __floats2half2_rn(acc[mt][nt][0] * iv0, acc[mt][nt][1] * iv0);
                    *(__half2*)(xb + ((size_t)(q2 * Bn + b2)) * Dm + branch * C2 + c2) = hv;
                }
                if (m0 + 8 < Qq) {
                    int f = (((b * Qq + m0 + 8) << 2) + h) * 64 + n0;
                    int q2 = f >> 11, rem = f & 2047, b2 = rem >> 8, c2 = rem & 255;
                    __half2 hv = __floats2half2_rn(acc[mt][nt][2] * iv1, acc[mt][nt][3] * iv1);
                    *(__half2*)(xb + ((size_t)(q2 * Bn + b2)) * Dm + branch * C2 + c2) = hv;
                }
            }
        }
    }
}

// ---------------------------------------------------------------------------
// host side
// ---------------------------------------------------------------------------
static int add_seg(GemmP& g, int idx, int start,
                   const __half* A, const __half* B, float* C, __half* Ch,
                   const float* bias, float scale,
                   int M, int N, int K, int mode,
                   int lda = 0, int ldb = 0) {
    GSeg& s = g.s[idx];
    s.A = A; s.B = B; s.C = C; s.Ch = Ch; s.bias = bias; s.scale = scale;
    s.M = M; s.N = N; s.K = K; s.mode = mode;
    s.lda = lda ? lda : K;
    s.ldb = ldb ? ldb : K;
    s.start = start;
    s.tilesX = N / 128;
    int tilesY = (M + 127) / 128;
    return start + s.tilesX * tilesY;
}

extern "C" void kernel_launch(void* const* d_in, const int* in_sizes, int n_in,
                              void* d_out, int out_size) {
    const float* query = (const float*)d_in[0];
    const float* key   = (const float*)d_in[1];
    const float* value = (const float*)d_in[2];
    const float* q_w   = (const float*)d_in[3];
    const float* sr11w = (const float*)d_in[4];
    const float* sr11b = (const float*)d_in[5];
    const float* n11g  = (const float*)d_in[6];
    const float* n11b  = (const float*)d_in[7];
    const float* sr12w = (const float*)d_in[8];
    const float* sr12b = (const float*)d_in[9];
    const float* n12g  = (const float*)d_in[10];
    const float* n12b  = (const float*)d_in[11];
    const float* sr21w = (const float*)d_in[12];
    const float* sr21b = (const float*)d_in[13];
    const float* n21g  = (const float*)d_in[14];
    const float* n21b  = (const float*)d_in[15];
    const float* sr22w = (const float*)d_in[16];
    const float* sr22b = (const float*)d_in[17];
    const float* n22g  = (const float*)d_in[18];
    const float* n22b  = (const float*)d_in[19];
    const float* k1w   = (const float*)d_in[20];
    const float* v1w   = (const float*)d_in[21];
    const float* k2w   = (const float*)d_in[22];
    const float* v2w   = (const float*)d_in[23];
    const float* lc1w  = (const float*)d_in[24];
    const float* lc1b  = (const float*)d_in[25];
    const float* lc2w  = (const float*)d_in[26];
    const float* lc2b  = (const float*)d_in[27];
    const float* projw = (const float*)d_in[28];
    const float* projb = (const float*)d_in[29];
    float* out = (float*)d_out;

    cudaFuncSetAttribute(k_gemm, cudaFuncAttributeMaxDynamicSharedMemorySize, GSMEM_BYTES);
    cudaFuncSetAttribute(k_attn_s, cudaFuncAttributeMaxDynamicSharedMemorySize, ASMEM_BYTES);
    cudaFuncSetAttribute(k_attn_o, cudaFuncAttributeMaxDynamicSharedMemorySize, GSMEM_BYTES);

    __half* hh;
    float* ff;
    cudaGetSymbolAddress((void**)&hh, g_h);
    cudaGetSymbolAddress((void**)&ff, g_f);

    auto grd = [](long long total) { return (unsigned)((total + 255) / 256); };

    // 0. conv-weight transposes -> fp16
    {
        TwP tp;
        tp.src[0] = sr11w; tp.dst[0] = hh + H_W11T;
        tp.src[1] = sr12w; tp.dst[1] = hh + H_W12T;
        tp.src[2] = sr21w; tp.dst[2] = hh + H_W21T;
        tp.src[3] = sr22w; tp.dst[3] = hh + H_W22T;
        k_tw_conv<<<dim3(512, 4), 256>>>(tp);
    }
    // 1. linear weights + activations -> fp16 (flattened grid)
    {
        PrepH pa;
        const float* srcs[9] = {q_w, projw, k1w, v1w, k2w, v2w, query, key, value};
        __half* dsts[9] = {hh + H_QWR, hh + H_PWR, hh + H_KW1R, hh + H_VW1R,
                           hh + H_KW2R, hh + H_VW2R, hh + H_QR, hh + H_KEYR, hh + H_VALR};
        long long n4s[9] = {512 * 512 / 4, 512 * 512 / 4, 256 * 512 / 4, 256 * 512 / 4,
                            256 * 512 / 4, 256 * 512 / 4, (long long)MQ * 512 / 4,
                            (long long)Bn * Nn * 512 / 4, (long long)Bn * Nn * 512 / 4};
        int s = 0;
        for (int i = 0; i < 9; i++) {
            pa.src[i] = srcs[i];
            pa.dst[i] = dsts[i];
            pa.start[i] = s;
            s += (int)(n4s[i] / 256);
        }
        pa.start[9] = s;
        k_prep<<<s, 256>>>(pa);
    }
    // 2. slot alignment (profile slot 3 = GEMM1)
    k_nop<<<1, 32>>>();
    // 3. merged GEMM #1 — split-K conv1 (2x64-chunk halves), LPT order
    //    A offset for patch half 2: +2 image rows (p -> p+8).
    {
        GemmP g;
        int s = 0;
        const __half* keyB = hh + H_KEYR + (size_t)2 * Ww * Dm;
        const __half* valB = hh + H_VALR + (size_t)2 * Ww * Dm;
        s = add_seg(g, 0, s, hh + H_KEYR, hh + H_W11T,        ff + S_C1K,  nullptr, nullptr, 1.f, M1, 512, 4096, 1, 0, K1);
        s = add_seg(g, 1, s, keyB,        hh + H_W11T + 4096, ff + S_C1KB, nullptr, nullptr, 1.f, M1, 512, 4096, 1, 0, K1);
        s = add_seg(g, 2, s, hh + H_VALR, hh + H_W12T,        ff + S_C1V,  nullptr, nullptr, 1.f, M1, 512, 4096, 1, 0, K1);
        s = add_seg(g, 3, s, valB,        hh + H_W12T + 4096, ff + S_C1VB, nullptr, nullptr, 1.f, M1, 512, 4096, 1, 0, K1);
        s = add_seg(g, 4, s, hh + H_KEYR, hh + H_W21T, ff + S_C2K, nullptr, nullptr, 1.f, M2, 512, K2, 2);
        s = add_seg(g, 5, s, hh + H_VALR, hh + H_W22T, ff + S_C2V, nullptr, nullptr, 1.f, M2, 512, K2, 2);
        s = add_seg(g, 6, s, hh + H_QR,   hh + H_QWR,  nullptr, hh + H_PQ, nullptr, 0.125f, MQ, 512, 512, 0);
        g.nseg = 7;
        k_gemm<<<s, 256, GSMEM_BYTES>>>(g);
    }
    // 4. LN -> fp16 (warp-per-row; branch1 sums split-K halves)
    {
        LnP p;
        p.x[0] = ff + S_C1K; p.x2[0] = ff + S_C1KB; p.cb[0] = sr11b; p.g[0] = n11g; p.b[0] = n11b; p.o[0] = hh + H_LN1K;
        p.x[1] = ff + S_C1V; p.x2[1] = ff + S_C1VB; p.cb[1] = sr12b; p.g[1] = n12g; p.b[1] = n12b; p.o[1] = hh + H_LN1V;
        p.x[2] = ff + S_C2K; p.x2[2] = nullptr;     p.cb[2] = sr21b; p.g[2] = n21g; p.b[2] = n21b; p.o[2] = hh + H_LN2K;
        p.x[3] = ff + S_C2V; p.x2[3] = nullptr;     p.cb[3] = sr22b; p.g[3] = n22g; p.b[3] = n22b; p.o[3] = hh + H_LN2V;
        k_biasln<<<(LNROWS + 7) / 8, 256>>>(p);
    }
    // 5. merged GEMM #2
    {
        GemmP g;
        int s = 0;
        s = add_seg(g, 0, s, hh + H_LN2K, hh + H_KW2R, nullptr, hh + H_KB2, nullptr, 1.f, M2, 256, 512, 0);
        s = add_seg(g, 1, s, hh + H_LN2V, hh + H_VW2R, ff + S_VB2, nullptr, nullptr, 1.f, M2, 256, 512, 0);
        s = add_seg(g, 2, s, hh + H_LN1K, hh + H_KW1R, nullptr, hh + H_KB1, nullptr, 1.f, M1, 256, 512, 0);
        s = add_seg(g, 3, s, hh + H_LN1V, hh + H_VW1R, ff + S_VB1, nullptr, nullptr, 1.f, M1, 256, 512, 0);
        g.nseg = 4;
        k_gemm<<<s, 256, GSMEM_BYTES>>>(g);
    }
    // 6. depthwise local V + residual -> fp16
    {
        DwP p;
        p.v[0] = ff + S_VB1; p.vs[0] = hh + H_VS1; p.lw[0] = lc1w; p.lb[0] = lc1b;
        p.v[1] = ff + S_VB2; p.vs[1] = hh + H_VS2; p.lw[1] = lc2w; p.lb[1] = lc2b;
        k_dwadd<<<grd((long long)(M1 + M2) * 128), 256>>>(p);
    }
    // 7. attention scores
    {
        AttnSP p;
        p.Qh = hh + H_PQ;
        p.Kh[0] = hh + H_KB1; p.Kh[1] = hh + H_KB2;
        p.S[0] = ff + S_S1;   p.S[1] = ff + S_S2;
        k_attn_s<<<dim3(16, 8, 8), 256, ASMEM_BYTES>>>(p);
    }
    // 8. softmax
    {
        SmP p;
        p.S[0] = ff + S_S1; p.S[1] = ff + S_S2;
        p.P[0] = hh + H_P1; p.P[1] = hh + H_P2;
        p.inv[0] = ff + S_INV1; p.inv[1] = ff + S_INV2;
        k_softmax<<<(2 * ROWS1) / 8, 256>>>(p);
    }
    // 9. attention output (V direct from VS via ldmatrix.trans)
    {
        AttnOP p;
        p.P[0] = hh + H_P1; p.P[1] = hh + H_P2;
        p.VS[0] = hh + H_VS1; p.VS[1] = hh + H_VS2;
        p.inv[0] = ff + S_INV1; p.inv[1] = ff + S_INV2;
        p.xbuf = hh + H_X;
        k_attn_o<<<dim3(2, 8, 8), 256, GSMEM_BYTES>>>(p);
    }
    // 10. final projection (+bias)
    {
        GemmP g;
        int s = add_seg(g, 0, 0, hh + H_X, hh + H_PWR, out, nullptr, projb, 1.f, MQ, 512, 512, 0);
        g.nseg = 1;
        k_gemm<<<s, 256, GSMEM_BYTES>>>(g);
    }

    (void)in_sizes; (void)n_in; (void)out_size;
}

// round 16
// speedup vs baseline: 1.4541x; 1.4541x over previous
#include <cuda_runtime.h>
#include <cuda_fp16.h>
#include <cstdint>
#include <cstddef>

// ---------------------------------------------------------------------------
// Problem constants
// ---------------------------------------------------------------------------
#define Dm    512
#define Bn    8
#define Hh    64
#define Ww    64
#define Nn    (Hh*Ww)      // 4096
#define Qq    200
#define C2    256
#define NH    8
#define NH2   4
#define HD    64
#define L1    256
#define L2    1024
#define M1    (Bn*L1)      // 2048
#define M2    (Bn*L2)      // 8192
#define K1    (Dm*16)      // 8192
#define K2    (Dm*4)       // 2048
#define MQ    (Qq*Bn)      // 1600
#define NBH   32
#define ROWS1 (NBH*Qq)     // 6400
#define LNROWS (2*(M1+M2)) // 20480

// ---------------------------------------------------------------------------
// scratch pools
// ---------------------------------------------------------------------------
constexpr size_t H_W11T = 0;
constexpr size_t H_W12T = H_W11T + 512u*8192u;
constexpr size_t H_W21T = H_W12T + 512u*8192u;
constexpr size_t H_W22T = H_W21T + 512u*2048u;
constexpr size_t H_QWR  = H_W22T + 512u*2048u;
constexpr size_t H_PWR  = H_QWR  + 512u*512u;
constexpr size_t H_KW1R = H_PWR  + 512u*512u;
constexpr size_t H_VW1R = H_KW1R + 256u*512u;
constexpr size_t H_KW2R = H_VW1R + 256u*512u;
constexpr size_t H_VW2R = H_KW2R + 256u*512u;
constexpr size_t H_QR   = H_VW2R + 256u*512u;
constexpr size_t H_KEYR = H_QR   + (size_t)MQ*512u;
constexpr size_t H_VALR = H_KEYR + (size_t)Bn*Nn*512u;
constexpr size_t H_LN1K = H_VALR + (size_t)Bn*Nn*512u;
constexpr size_t H_LN1V = H_LN1K + (size_t)M1*512u;
constexpr size_t H_LN2K = H_LN1V + (size_t)M1*512u;
constexpr size_t H_LN2V = H_LN2K + (size_t)M2*512u;
constexpr size_t H_PQ   = H_LN2V + (size_t)M2*512u;
constexpr size_t H_KB1  = H_PQ   + (size_t)MQ*512u;
constexpr size_t H_KB2  = H_KB1  + (size_t)M1*256u;
constexpr size_t H_VS1  = H_KB2  + (size_t)M2*256u;
constexpr size_t H_VS2  = H_VS1  + (size_t)M1*256u;
constexpr size_t H_P1   = H_VS2  + (size_t)M2*256u;
constexpr size_t H_P2   = H_P1   + (size_t)ROWS1*L1;
constexpr size_t H_X    = H_P2   + (size_t)ROWS1*L2;
constexpr size_t H_TOTAL = H_X   + (size_t)MQ*512u;

__device__ __align__(16) __half g_h[H_TOTAL];

constexpr size_t S_C1K  = 0;
constexpr size_t S_C1KB = S_C1K  + (size_t)M1*512u;
constexpr size_t S_C1V  = S_C1KB + (size_t)M1*512u;
constexpr size_t S_C1VB = S_C1V  + (size_t)M1*512u;
constexpr size_t S_C2K  = S_C1VB + (size_t)M1*512u;
constexpr size_t S_C2V  = S_C2K  + (size_t)M2*512u;
constexpr size_t S_VB1  = S_C2V  + (size_t)M2*512u;
constexpr size_t S_VB2  = S_VB1  + (size_t)M1*256u;
constexpr size_t S_S1   = S_VB2  + (size_t)M2*256u;
constexpr size_t S_S2   = S_S1   + (size_t)ROWS1*L1;
constexpr size_t S_INV1 = S_S2   + (size_t)ROWS1*L2;
constexpr size_t S_INV2 = S_INV1 + ROWS1;
constexpr size_t S_TOTAL = S_INV2 + ROWS1;

__device__ __align__(16) float g_f[S_TOTAL];

// ---------------------------------------------------------------------------
// helpers
// ---------------------------------------------------------------------------
__device__ __forceinline__ uint32_t smem_u32(const void* p) {
    uint32_t a;
    asm("{ .reg .u64 t; cvta.to.shared.u64 t, %1; cvt.u32.u64 %0, t; }" : "=r"(a) : "l"(p));
    return a;
}

#define MMA_F16(c, a, b) \
    asm volatile("mma.sync.aligned.m16n8k16.row.col.f32.f16.f16.f32 " \
        "{%0,%1,%2,%3}, {%4,%5,%6,%7}, {%8,%9}, {%0,%1,%2,%3};" \
        : "+f"((c)[0]), "+f"((c)[1]), "+f"((c)[2]), "+f"((c)[3]) \
        : "r"((a)[0]), "r"((a)[1]), "r"((a)[2]), "r"((a)[3]), \
          "r"((b)[0]), "r"((b)[1]))

#define LDSM4(r0, r1, r2, r3, addr) \
    asm volatile("ldmatrix.sync.aligned.m8n8.x4.shared.b16 {%0,%1,%2,%3}, [%4];" \
        : "=r"(r0), "=r"(r1), "=r"(r2), "=r"(r3) : "r"(addr))

#define LDSM4T(r0, r1, r2, r3, addr) \
    asm volatile("ldmatrix.sync.aligned.m8n8.x4.trans.shared.b16 {%0,%1,%2,%3}, [%4];" \
        : "=r"(r0), "=r"(r1), "=r"(r2), "=r"(r3) : "r"(addr))

__global__ void k_nop() {}

// ---------------------------------------------------------------------------
// Conv-weight transpose -> fp16
// ---------------------------------------------------------------------------
struct TwP {
    const float* src[4];
    __half* dst[4];
};
__global__ void __launch_bounds__(256) k_tw_conv(TwP tp) {
    __shared__ float smem[512 * 17];
    int seg = blockIdx.y;
    int co = blockIdx.x;
    int P = (seg < 2) ? 16 : 4;
    int pad = P + 1;
    int n = 512 * P;
    const float* s = tp.src[seg] + (size_t)co * n;
    __half* d = tp.dst[seg] + (size_t)co * n;
    for (int i = threadIdx.x; i < n; i += 256) {
        int ci = i / P, p = i % P;
        smem[ci * pad + p] = s[i];
    }
    __syncthreads();
    for (int j = threadIdx.x; j < n; j += 256) {
        int p = j >> 9, ci = j & 511;
        d[j] = __float2half_rn(smem[ci * pad + p]);
    }
}

// ---------------------------------------------------------------------------
// float4 -> half4 convert, flattened 1-D grid
// ---------------------------------------------------------------------------
struct PrepH {
    const float* src[9];
    __half* dst[9];
    int start[10];
};
__global__ void k_prep(PrepH pa) {
    int blk = blockIdx.x;
    int seg = 0;
    #pragma unroll
    for (int i = 1; i < 9; i++)
        if (blk >= pa.start[i]) seg = i;
    long long i = (long long)(blk - pa.start[seg]) * 256 + threadIdx.x;
    float4 v = ((const float4*)pa.src[seg])[i];
    __half2 h0 = __floats2half2_rn(v.x, v.y);
    __half2 h1 = __floats2half2_rn(v.z, v.w);
    uint2 o;
    o.x = *reinterpret_cast<uint32_t*>(&h0);
    o.y = *reinterpret_cast<uint32_t*>(&h1);
    ((uint2*)pa.dst[seg])[i] = o;
}

// ---------------------------------------------------------------------------
// FP16 GEMM, multi-segment (up to 7).  2-stage double buffer, ldmatrix.
// lda/ldb allow split-K segments (B row stride != segment K).
// ---------------------------------------------------------------------------
struct GSeg {
    const __half* A;
    const __half* B;
    float* C;
    __half* Ch;
    const float* bias;
    float scale;
    int M, N, K, lda, ldb, mode, start, tilesX;
};
struct GemmP {
    GSeg s[7];
    int nseg;
};

#define PITCHH 72
#define PLANEB (128 * PITCHH * 2)       // 18432
#define STAGEB (2 * PLANEB)             // 36864
#define GSMEM_BYTES (2 * STAGEB)        // 73728

__global__ void __launch_bounds__(256, 2) k_gemm(GemmP g) {
    extern __shared__ char smc[];
    int si = 0;
    #pragma unroll
    for (int i = 1; i < 7; i++)
        if (i < g.nseg && (int)blockIdx.x >= g.s[i].start) si = i;
    const __half* A = g.s[si].A;
    const __half* B = g.s[si].B;
    float* C = g.s[si].C;
    __half* Ch = g.s[si].Ch;
    const float* bias = g.s[si].bias;
    float scale = g.s[si].scale;
    int M = g.s[si].M, N = g.s[si].N, K = g.s[si].K, mode = g.s[si].mode;
    int lda = g.s[si].lda, ldb = g.s[si].ldb;
    int t0 = blockIdx.x - g.s[si].start;
    int colBase = (t0 % g.s[si].tilesX) * 128;
    int rowBase = (t0 / g.s[si].tilesX) * 128;
    int tid = threadIdx.x, wid = tid >> 5, lane = tid & 31;
    int wm = wid & 1, wn = wid >> 1;
    uint32_t sb = smem_u32(smc);

    auto issue = [&](int stage, int kb) {
        uint32_t sbase = sb + stage * STAGEB;
        #pragma unroll
        for (int t = 0; t < 4; t++) {
            int cid = tid + t * 256;
            int r = cid >> 3, ch = cid & 7;
            int grow = rowBase + r;
            const __half* src;
            int sz = 16;
            if (mode == 0) {
                if (grow >= M) { sz = 0; grow = 0; }
                src = A + (size_t)grow * lda + kb + ch * 8;
            } else if (mode == 1) {
                int b = grow >> 8, rem = grow & 255;
                int oy = rem >> 4, ox = rem & 15;
                int p = kb >> 9;
                int y = oy * 4 + (p >> 2), x = ox * 4 + (p & 3);
                src = A + (((size_t)((b << 12) + (y << 6) + x)) << 9) + (kb & 511) + ch * 8;
            } else {
                int b = grow >> 10, oy = (grow >> 5) & 31, ox = grow & 31;
                int p = kb >> 9;
                int y = oy * 2 + (p >> 1), x = ox * 2 + (p & 1);
                src = A + (((size_t)((b << 12) + (y << 6) + x)) << 9) + (kb & 511) + ch * 8;
            }
            uint32_t sa = sbase + (uint32_t)(r * (PITCHH * 2)) + ch * 16;
            asm volatile("cp.async.cg.shared.global [%0], [%1], 16, %2;"
                         :: "r"(sa), "l"(src), "r"(sz) : "memory");
        }
        #pragma unroll
        for (int t = 0; t < 4; t++) {
            int cid = tid + t * 256;
            int r = cid >> 3, ch = cid & 7;
            const __half* src = B + (size_t)(colBase + r) * ldb + kb + ch * 8;
            uint32_t sa = sbase + PLANEB + (uint32_t)(r * (PITCHH * 2)) + ch * 16;
            asm volatile("cp.async.cg.shared.global [%0], [%1], 16, 16;"
                         :: "r"(sa), "l"(src) : "memory");
        }
        asm volatile("cp.async.commit_group;" ::: "memory");
    };

    float acc[4][4][4];
    #pragma unroll
    for (int a = 0; a < 4; a++)
        #pragma unroll
        for (int b = 0; b < 4; b++)
            #pragma unroll
            for (int c = 0; c < 4; c++) acc[a][b][c] = 0.f;

    uint32_t aoff[4], boff[2];
    {
        int rIn = (lane & 7) + (((lane >> 3) & 1) << 3);
        int kA = (lane >> 4) << 3;
        #pragma unroll
        for (int mt = 0; mt < 4; mt++)
            aoff[mt] = (uint32_t)(((wm * 64 + mt * 16 + rIn) * PITCHH + kA) * 2);
        int rB = ((lane >> 4) << 3) + (lane & 7);
        int kB = ((lane >> 3) & 1) << 3;
        #pragma unroll
        for (int bp = 0; bp < 2; bp++)
            boff[bp] = (uint32_t)(PLANEB + ((wn * 32 + bp * 16 + rB) * PITCHH + kB) * 2);
    }

    int niter = K >> 6;
    issue(0, 0);
    int r4 = lane >> 2, c4 = lane & 3;

    for (int it = 0; it < niter; it++) {
        if (it + 1 < niter) {
            issue((it + 1) & 1, (it + 1) << 6);
            asm volatile("cp.async.wait_group 1;" ::: "memory");
        } else {
            asm volatile("cp.async.wait_group 0;" ::: "memory");
        }
        __syncthreads();
        uint32_t sbase = sb + (it & 1) * STAGEB;

        #pragma unroll
        for (int kk = 0; kk < 64; kk += 16) {
            uint32_t af[4][4], bf_[4][2];
            uint32_t kb2 = kk * 2;
            #pragma unroll
            for (int mt = 0; mt < 4; mt++)
                LDSM4(af[mt][0], af[mt][1], af[mt][2], af[mt][3], sbase + aoff[mt] + kb2);
            LDSM4(bf_[0][0], bf_[0][1], bf_[1][0], bf_[1][1], sbase + boff[0] + kb2);
            LDSM4(bf_[2][0], bf_[2][1], bf_[3][0], bf_[3][1], sbase + boff[1] + kb2);
            #pragma unroll
            for (int mt = 0; mt < 4; mt++)
                #pragma unroll
                for (int nt = 0; nt < 4; nt++)
                    MMA_F16(acc[mt][nt], af[mt], bf_[nt]);
        }
        __syncthreads();
    }

    #pragma unroll
    for (int mt = 0; mt < 4; mt++) {
        #pragma unroll
        for (int nt = 0; nt < 4; nt++) {
            int m0 = rowBase + wm * 64 + mt * 16 + r4;
            int n0 = colBase + wn * 32 + nt * 8 + 2 * c4;
            if (Ch) {
                if (m0 < M) {
                    __half2 hv = __floats2half2_rn(acc[mt][nt][0] * scale, acc[mt][nt][1] * scale);
                    *(__half2*)(Ch + (size_t)m0 * N + n0) = hv;
                }
                if (m0 + 8 < M) {
                    __half2 hv = __floats2half2_rn(acc[mt][nt][2] * scale, acc[mt][nt][3] * scale);
                    *(__half2*)(Ch + (size_t)(m0 + 8) * N + n0) = hv;
                }
            } else {
                float bx = 0.f, by = 0.f;
                if (bias) { bx = bias[n0]; by = bias[n0 + 1]; }
                if (m0 < M) {
                    float2 v = make_float2(acc[mt][nt][0] + bx, acc[mt][nt][1] + by);
                    *(float2*)(C + (size_t)m0 * N + n0) = v;
                }
                if (m0 + 8 < M) {
                    float2 v = make_float2(acc[mt][nt][2] + bx, acc[mt][nt][3] + by);
                    *(float2*)(C + (size_t)(m0 + 8) * N + n0) = v;
                }
            }
        }
    }
}

// ---------------------------------------------------------------------------
// bias + LayerNorm(512) + relu6 -> fp16.  Warp-per-row.  Optional second
// input (split-K partial sums) added on load.
// ---------------------------------------------------------------------------
struct LnP {
    const float* x[4];
    const float* x2[4];
    const float* cb[4];
    const float* g[4];
    const float* b[4];
    __half* o[4];
};
__global__ void __launch_bounds__(256) k_biasln(LnP p) {
    int gr = blockIdx.x * 8 + (threadIdx.x >> 5);
    int lane = threadIdx.x & 31;
    if (gr >= LNROWS) return;
    int seg, row;
    if (gr < M1) { seg = 0; row = gr; }
    else if (gr < 2 * M1) { seg = 1; row = gr - M1; }
    else if (gr < 2 * M1 + M2) { seg = 2; row = gr - 2 * M1; }
    else { seg = 3; row = gr - 2 * M1 - M2; }
    const float* xr = p.x[seg] + (size_t)row * 512;
    const float* x2r = p.x2[seg] ? p.x2[seg] + (size_t)row * 512 : nullptr;
    const float* cb = p.cb[seg];
    const float* gg = p.g[seg];
    const float* bb = p.b[seg];
    __half* orow = p.o[seg] + (size_t)row * 512;

    float4 v[4];
    float s = 0.f;
    #pragma unroll
    for (int i = 0; i < 4; i++) {
        int off = lane * 4 + i * 128;
        float4 xv = *(const float4*)(xr + off);
        float4 cv = *(const float4*)(cb + off);
        v[i] = make_float4(xv.x + cv.x, xv.y + cv.y, xv.z + cv.z, xv.w + cv.w);
        if (x2r) {
            float4 x2v = *(const float4*)(x2r + off);
            v[i].x += x2v.x; v[i].y += x2v.y; v[i].z += x2v.z; v[i].w += x2v.w;
        }
        s += v[i].x + v[i].y + v[i].z + v[i].w;
    }
    #pragma unroll
    for (int off = 16; off; off >>= 1) s += __shfl_xor_sync(0xffffffffu, s, off);
    float mean = s * (1.f / 512.f);
    float s2 = 0.f;
    #pragma unroll
    for (int i = 0; i < 4; i++) {
        v[i].x -= mean; v[i].y -= mean; v[i].z -= mean; v[i].w -= mean;
        s2 += v[i].x * v[i].x + v[i].y * v[i].y + v[i].z * v[i].z + v[i].w * v[i].w;
    }
    #pragma unroll
    for (int off = 16; off; off >>= 1) s2 += __shfl_xor_sync(0xffffffffu, s2, off);
    float inv = rsqrtf(s2 * (1.f / 512.f) + 1e-5f);
    #pragma unroll
    for (int i = 0; i < 4; i++) {
        int off = lane * 4 + i * 128;
        float4 gv = *(const float4*)(gg + off);
        float4 bv = *(const float4*)(bb + off);
        float y0 = fminf(fmaxf(v[i].x * inv * gv.x + bv.x, 0.f), 6.f);
        float y1 = fminf(fmaxf(v[i].y * inv * gv.y + bv.y, 0.f), 6.f);
        float y2 = fminf(fmaxf(v[i].z * inv * gv.z + bv.z, 0.f), 6.f);
        float y3 = fminf(fmaxf(v[i].w * inv * gv.w + bv.w, 0.f), 6.f);
        __half2 h0 = __floats2half2_rn(y0, y1);
        __half2 h1 = __floats2half2_rn(y2, y3);
        uint2 o;
        o.x = *reinterpret_cast<uint32_t*>(&h0);
        o.y = *reinterpret_cast<uint32_t*>(&h1);
        *(uint2*)(orow + off) = o;
    }
}

// ---------------------------------------------------------------------------
// depthwise 3x3 (pad 1) + bias + residual -> fp16, channel-pair vectorized
// ---------------------------------------------------------------------------
struct DwP {
    const float* v[2];
    __half* vs[2];
    const float* lw[2];
    const float* lb[2];
};
__global__ void k_dwadd(DwP p) {
    long long idx = (long long)blockIdx.x * 256 + threadIdx.x;
    const long long tot1 = (long long)M1 * 128;
    const long long tot2 = (long long)M2 * 128;
    int br;
    long long li;
    if (idx < tot1) { br = 0; li = idx; }
    else { idx -= tot1; if (idx >= tot2) return; br = 1; li = idx; }
    int hh = br ? 32 : 16, ww = hh;
    int L = hh * ww;
    int c = (int)(li & 127) << 1;
    int l = (int)((li >> 7) % L);
    int b = (int)(li / ((long long)L << 7));
    int y = l / ww, x = l % ww;
    const float* v = p.v[br];
    const float* lw = p.lw[br];
    float2 acc = make_float2(p.lb[br][c], p.lb[br][c + 1]);
    #pragma unroll
    for (int dy = 0; dy < 3; dy++) {
        int yy = y + dy - 1;
        if ((unsigned)yy >= (unsigned)hh) continue;
        #pragma unroll
        for (int dx = 0; dx < 3; dx++) {
            int xx = x + dx - 1;
            if ((unsigned)xx >= (unsigned)ww) continue;
            float2 vv = *(const float2*)&v[(((long long)b * L + yy * ww + xx) << 8) + c];
            int t = dy * 3 + dx;
            acc.x += vv.x * lw[c * 9 + t];
            acc.y += vv.y * lw[(c + 1) * 9 + t];
        }
    }
    float2 v0 = *(const float2*)&v[li << 1];
    *(__half2*)&p.vs[br][li << 1] = __floats2half2_rn(v0.x + acc.x, v0.y + acc.y);
}

// ---------------------------------------------------------------------------
// Attention S = Q @ K^T.  128x128 fp16 MMA, K=64, ldmatrix loads.
// Flattened 1-D grid: 128 branch-0 blocks then 512 branch-1 blocks (no ghosts).
// ---------------------------------------------------------------------------
struct AttnSP {
    const __half* Qh;
    const __half* Kh[2];
    float* S[2];
};
#define ASMEM_BYTES STAGEB

__global__ void __launch_bounds__(256) k_attn_s(AttnSP p) {
    extern __shared__ char smc[];
    int idx = blockIdx.x;
    int branch, xh, h, b;
    if (idx < 128) { branch = 0; xh = idx & 3; h = (idx >> 2) & 3; b = idx >> 4; }
    else { idx -= 128; branch = 1; xh = idx & 15; h = (idx >> 4) & 3; b = idx >> 6; }
    int hg = branch * 4 + h;
    int L = branch ? L2 : L1;
    int lt = xh >> 1, mt_ = xh & 1;
    int rowBase = mt_ * 128, colBase = lt * 128;
    int tid = threadIdx.x, wid = tid >> 5, lane = tid & 31;
    int wm = wid & 1, wn = wid >> 1;
    uint32_t sb = smem_u32(smc);
    const __half* Qh = p.Qh;
    const __half* Kh = p.Kh[branch];

    #pragma unroll
    for (int t = 0; t < 4; t++) {
        int cid = tid + t * 256;
        int r = cid >> 3, ch = cid & 7;
        int q = rowBase + r;
        int sz = (q < Qq) ? 16 : 0;
        int qc = sz ? q : 0;
        const __half* src = Qh + ((size_t)(b * Qq + qc) * NH + hg) * 64 + ch * 8;
        uint32_t sa = sb + (uint32_t)(r * (PITCHH * 2)) + ch * 16;
        asm volatile("cp.async.cg.shared.global [%0], [%1], 16, %2;"
                     :: "r"(sa), "l"(src), "r"(sz) : "memory");
        int l = colBase + r;
        const __half* srcB = Kh + ((size_t)(b * L + l)) * 256 + h * 64 + ch * 8;
        uint32_t sab = sb + PLANEB + (uint32_t)(r * (PITCHH * 2)) + ch * 16;
        asm volatile("cp.async.cg.shared.global [%0], [%1], 16, 16;"
                     :: "r"(sab), "l"(srcB) : "memory");
    }
    asm volatile("cp.async.commit_group;" ::: "memory");
    asm volatile("cp.async.wait_group 0;" ::: "memory");
    __syncthreads();

    float acc[4][4][4];
    #pragma unroll
    for (int a = 0; a < 4; a++)
        #pragma unroll
        for (int bb = 0; bb < 4; bb++)
            #pragma unroll
            for (int c = 0; c < 4; c++) acc[a][bb][c] = 0.f;

    uint32_t aoff[4], boff[2];
    {
        int rIn = (lane & 7) + (((lane >> 3) & 1) << 3);
        int kA = (lane >> 4) << 3;
        #pragma unroll
        for (int mt = 0; mt < 4; mt++)
            aoff[mt] = (uint32_t)(((wm * 64 + mt * 16 + rIn) * PITCHH + kA) * 2);
        int rB = ((lane >> 4) << 3) + (lane & 7);
        int kB = ((lane >> 3) & 1) << 3;
        #pragma unroll
        for (int bp = 0; bp < 2; bp++)
            boff[bp] = (uint32_t)(PLANEB + ((wn * 32 + bp * 16 + rB) * PITCHH + kB) * 2);
    }
    int r4 = lane >> 2, c4 = lane & 3;

    #pragma unroll
    for (int kk = 0; kk < 64; kk += 16) {
        uint32_t af[4][4], bf_[4][2];
        uint32_t kb2 = kk * 2;
        #pragma unroll
        for (int mt = 0; mt < 4; mt++)
            LDSM4(af[mt][0], af[mt][1], af[mt][2], af[mt][3], sb + aoff[mt] + kb2);
        LDSM4(bf_[0][0], bf_[0][1], bf_[1][0], bf_[1][1], sb + boff[0] + kb2);
        LDSM4(bf_[2][0], bf_[2][1], bf_[3][0], bf_[3][1], sb + boff[1] + kb2);
        #pragma unroll
        for (int mt = 0; mt < 4; mt++)
            #pragma unroll
            for (int nt = 0; nt < 4; nt++)
                MMA_F16(acc[mt][nt], af[mt], bf_[nt]);
    }

    float* Sb = p.S[branch] + (size_t)((b * 4 + h) * Qq) * L;
    #pragma unroll
    for (int mt = 0; mt < 4; mt++) {
        #pragma unroll
        for (int nt = 0; nt < 4; nt++) {
            int m0 = rowBase + wm * 64 + mt * 16 + r4;
            int n0 = colBase + wn * 32 + nt * 8 + 2 * c4;
            if (m0 < Qq)
                *(float2*)(Sb + (size_t)m0 * L + n0) =
                    make_float2(acc[mt][nt][0], acc[mt][nt][1]);
            if (m0 + 8 < Qq)
                *(float2*)(Sb + (size_t)(m0 + 8) * L + n0) =
                    make_float2(acc[mt][nt][2], acc[mt][nt][3]);
        }
    }
}

// ---------------------------------------------------------------------------
// softmax: one warp per row, float4 vectorized
// ---------------------------------------------------------------------------
struct SmP {
    const float* S[2];
    __half* P[2];
    float* inv[2];
};
__global__ void __launch_bounds__(256) k_softmax(SmP p) {
    int r = blockIdx.x * 8 + (threadIdx.x >> 5);
    int lane = threadIdx.x & 31;
    int branch = (r >= ROWS1) ? 1 : 0;
    int local = r - branch * ROWS1;
    int L = branch ? L2 : L1;
    const float* S = p.S[branch] + (size_t)local * L;
    __half* P = p.P[branch] + (size_t)local * L;
    int n4 = L >> 7;
    float m = -1e30f;
    for (int i = 0; i < n4; i++) {
        float4 v = *(const float4*)(S + (i * 128 + lane * 4));
        m = fmaxf(m, fmaxf(fmaxf(v.x, v.y), fmaxf(v.z, v.w)));
    }
    #pragma unroll
    for (int off = 16; off; off >>= 1) m = fmaxf(m, __shfl_xor_sync(0xffffffffu, m, off));
    float s = 0.f;
    for (int i = 0; i < n4; i++) {
        int off = i * 128 + lane * 4;
        float4 v = *(const float4*)(S + off);
        float e0 = __expf(v.x - m), e1 = __expf(v.y - m);
        float e2 = __expf(v.z - m), e3 = __expf(v.w - m);
        s += e0 + e1 + e2 + e3;
        __half2 h0 = __floats2half2_rn(e0, e1);
        __half2 h1 = __floats2half2_rn(e2, e3);
        uint2 o;
        o.x = *reinterpret_cast<uint32_t*>(&h0);
        o.y = *reinterpret_cast<uint32_t*>(&h1);
        *(uint2*)(P + off) = o;
    }
    #pragma unroll
    for (int off = 16; off; off >>= 1) s += __shfl_xor_sync(0xffffffffu, s, off);
    if (lane == 0) p.inv[branch][local] = 1.f / s;
}

// ---------------------------------------------------------------------------
// Attention O = P @ V, N=64, K=L; 2-stage double buffer; V via ldmatrix.trans.
// ---------------------------------------------------------------------------
struct AttnOP {
    const __half* P[2];
    const __half* VS[2];
    const float* inv[2];
    __half* xbuf;
};
__global__ void __launch_bounds__(256, 2) k_attn_o(AttnOP p) {
    extern __shared__ char smc[];
    int mt_ = blockIdx.x, hg = blockIdx.y, b = blockIdx.z;
    int branch = hg >> 2, h = hg & 3;
    int L = branch ? L2 : L1;
    int rowBase = mt_ * 128;
    int tid = threadIdx.x, wid = tid >> 5, lane = tid & 31;
    int wm = wid & 1, wn = wid >> 1;
    uint32_t sb = smem_u32(smc);
    const __half* Pm = p.P[branch] + (size_t)((b * 4 + h) * Qq) * L;
    const __half* VS = p.VS[branch];
    const float* inv = p.inv[branch] + (b * 4 + h) * Qq;

    auto issue = [&](int stage, int kb) {
        uint32_t sbase = sb + stage * STAGEB;
        #pragma unroll
        for (int t = 0; t < 4; t++) {
            int cid = tid + t * 256;
            int r = cid >> 3, ch = cid & 7;
            int q = rowBase + r;
            int sz = (q < Qq) ? 16 : 0;
            int qc = sz ? q : 0;
            const __half* src = Pm + (size_t)qc * L + kb + ch * 8;
            uint32_t sa = sbase + (uint32_t)(r * (PITCHH * 2)) + ch * 16;
            asm volatile("cp.async.cg.shared.global [%0], [%1], 16, %2;"
                         :: "r"(sa), "l"(src), "r"(sz) : "memory");
            int szb = (r < 64) ? 16 : 0;
            int rc = szb ? r : 0;
            const __half* srcB = VS + ((size_t)(b * L + kb + rc)) * 256 + h * 64 + ch * 8;
            uint32_t sab = sbase + PLANEB + (uint32_t)(r * (PITCHH * 2)) + ch * 16;
            asm volatile("cp.async.cg.shared.global [%0], [%1], 16, %2;"
                         :: "r"(sab), "l"(srcB), "r"(szb) : "memory");
        }
        asm volatile("cp.async.commit_group;" ::: "memory");
    };

    float acc[4][4][4];
    #pragma unroll
    for (int a = 0; a < 4; a++)
        #pragma unroll
        for (int bb = 0; bb < 4; bb++)
            #pragma unroll
            for (int c = 0; c < 4; c++) acc[a][bb][c] = 0.f;

    uint32_t aoff[4], boffT[2];
    {
        int rIn = (lane & 7) + (((lane >> 3) & 1) << 3);
        int kA = (lane >> 4) << 3;
        #pragma unroll
        for (int mt = 0; mt < 4; mt++)
            aoff[mt] = (uint32_t)(((wm * 64 + mt * 16 + rIn) * PITCHH + kA) * 2);
        int rT = (lane & 7) + (((lane >> 3) & 1) << 3);
        int nT0 = (lane >> 4) << 3;
        #pragma unroll
        for (int bp = 0; bp < 2; bp++)
            boffT[bp] = (uint32_t)(PLANEB + (rT * PITCHH + wn * 32 + bp * 16 + nT0) * 2);
    }

    int niter = L >> 6;
    issue(0, 0);
    int r4 = lane >> 2, c4 = lane & 3;

    for (int it = 0; it < niter; it++) {
        if (it + 1 < niter) {
            issue((it + 1) & 1, (it + 1) << 6);
            asm volatile("cp.async.wait_group 1;" ::: "memory");
        } else {
            asm volatile("cp.async.wait_group 0;" ::: "memory");
        }
        __syncthreads();
        uint32_t sbase = sb + (it & 1) * STAGEB;

        #pragma unroll
        for (int kk = 0; kk < 64; kk += 16) {
            uint32_t af[4][4], bf_[4][2];
            uint32_t kb2 = kk * 2;
            uint32_t krow = (uint32_t)kk * (PITCHH * 2);
            #pragma unroll
            for (int mt = 0; mt < 4; mt++)
                LDSM4(af[mt][0], af[mt][1], af[mt][2], af[mt][3], sbase + aoff[mt] + kb2);
            LDSM4T(bf_[0][0], bf_[0][1], bf_[1][0], bf_[1][1], sbase + boffT[0] + krow);
            LDSM4T(bf_[2][0], bf_[2][1], bf_[3][0], bf_[3][1], sbase + boffT[1] + krow);
            #pragma unroll
            for (int mt = 0; mt < 4; mt++)
                #pragma unroll
                for (int nt = 0; nt < 4; nt++)
                    MMA_F16(acc[mt][nt], af[mt], bf_[nt]);
        }
        __syncthreads();
    }

    __half* xb = p.xbuf;
    #pragma unroll
    for (int mt = 0; mt < 4; mt++) {
        int m0 = rowBase + wm * 64 + mt * 16 + r4;
        float iv0 = (m0 < Qq) ? inv[m0] : 0.f;
        float iv1 = (m0 + 8 < Qq) ? inv[m0 + 8] : 0.f;
        #pragma unroll
        for (int nt = 0; nt < 4; nt++) {
            int n0 = wn * 32 + nt * 8 + 2 * c4;
            if (n0 < 64) {
                if (m0 < Qq) {
                    int f = (((b * Qq + m0) << 2) + h) * 64 + n0;
                    int q2 = f >> 11, rem = f & 2047, b2 = rem >> 8, c2 = rem & 255;
                    __half2 hv = __floats2half2_rn(acc[mt][nt][0] * iv0, acc[mt][nt][1] * iv0);
                    *(__half2*)(xb + ((size_t)(q2 * Bn + b2)) * Dm + branch * C2 + c2) = hv;
                }
                if (m0 + 8 < Qq) {
                    int f = (((b * Qq + m0 + 8) << 2) + h) * 64 + n0;
                    int q2 = f >> 11, rem = f & 2047, b2 = rem >> 8, c2 = rem & 255;
                    __half2 hv = __floats2half2_rn(acc[mt][nt][2] * iv1, acc[mt][nt][3] * iv1);
                    *(__half2*)(xb + ((size_t)(q2 * Bn + b2)) * Dm + branch * C2 + c2) = hv;
                }
            }
        }
    }
}

// ---------------------------------------------------------------------------
// host side
// ---------------------------------------------------------------------------
static int add_seg(GemmP& g, int idx, int start,
                   const __half* A, const __half* B, float* C, __half* Ch,
                   const float* bias, float scale,
                   int M, int N, int K, int mode,
                   int lda = 0, int ldb = 0) {
    GSeg& s = g.s[idx];
    s.A = A; s.B = B; s.C = C; s.Ch = Ch; s.bias = bias; s.scale = scale;
    s.M = M; s.N = N; s.K = K; s.mode = mode;
    s.lda = lda ? lda : K;
    s.ldb = ldb ? ldb : K;
    s.start = start;
    s.tilesX = N / 128;
    int tilesY = (M + 127) / 128;
    return start + s.tilesX * tilesY;
}

extern "C" void kernel_launch(void* const* d_in, const int* in_sizes, int n_in,
                              void* d_out, int out_size) {
    const float* query = (const float*)d_in[0];
    const float* key   = (const float*)d_in[1];
    const float* value = (const float*)d_in[2];
    const float* q_w   = (const float*)d_in[3];
    const float* sr11w = (const float*)d_in[4];
    const float* sr11b = (const float*)d_in[5];
    const float* n11g  = (const float*)d_in[6];
    const float* n11b  = (const float*)d_in[7];
    const float* sr12w = (const float*)d_in[8];
    const float* sr12b = (const float*)d_in[9];
    const float* n12g  = (const float*)d_in[10];
    const float* n12b  = (const float*)d_in[11];
    const float* sr21w = (const float*)d_in[12];
    const float* sr21b = (const float*)d_in[13];
    const float* n21g  = (const float*)d_in[14];
    const float* n21b  = (const float*)d_in[15];
    const float* sr22w = (const float*)d_in[16];
    const float* sr22b = (const float*)d_in[17];
    const float* n22g  = (const float*)d_in[18];
    const float* n22b  = (const float*)d_in[19];
    const float* k1w   = (const float*)d_in[20];
    const float* v1w   = (const float*)d_in[21];
    const float* k2w   = (const float*)d_in[22];
    const float* v2w   = (const float*)d_in[23];
    const float* lc1w  = (const float*)d_in[24];
    const float* lc1b  = (const float*)d_in[25];
    const float* lc2w  = (const float*)d_in[26];
    const float* lc2b  = (const float*)d_in[27];
    const float* projw = (const float*)d_in[28];
    const float* projb = (const float*)d_in[29];
    float* out = (float*)d_out;

    cudaFuncSetAttribute(k_gemm, cudaFuncAttributeMaxDynamicSharedMemorySize, GSMEM_BYTES);
    cudaFuncSetAttribute(k_attn_s, cudaFuncAttributeMaxDynamicSharedMemorySize, ASMEM_BYTES);
    cudaFuncSetAttribute(k_attn_o, cudaFuncAttributeMaxDynamicSharedMemorySize, GSMEM_BYTES);

    __half* hh;
    float* ff;
    cudaGetSymbolAddress((void**)&hh, g_h);
    cudaGetSymbolAddress((void**)&ff, g_f);

    auto grd = [](long long total) { return (unsigned)((total + 255) / 256); };

    // 0. conv-weight transposes -> fp16
    {
        TwP tp;
        tp.src[0] = sr11w; tp.dst[0] = hh + H_W11T;
        tp.src[1] = sr12w; tp.dst[1] = hh + H_W12T;
        tp.src[2] = sr21w; tp.dst[2] = hh + H_W21T;
        tp.src[3] = sr22w; tp.dst[3] = hh + H_W22T;
        k_tw_conv<<<dim3(512, 4), 256>>>(tp);
    }
    // 1. linear weights + activations -> fp16 (flattened grid)
    {
        PrepH pa;
        const float* srcs[9] = {q_w, projw, k1w, v1w, k2w, v2w, query, key, value};
        __half* dsts[9] = {hh + H_QWR, hh + H_PWR, hh + H_KW1R, hh + H_VW1R,
                           hh + H_KW2R, hh + H_VW2R, hh + H_QR, hh + H_KEYR, hh + H_VALR};
        long long n4s[9] = {512 * 512 / 4, 512 * 512 / 4, 256 * 512 / 4, 256 * 512 / 4,
                            256 * 512 / 4, 256 * 512 / 4, (long long)MQ * 512 / 4,
                            (long long)Bn * Nn * 512 / 4, (long long)Bn * Nn * 512 / 4};
        int s = 0;
        for (int i = 0; i < 9; i++) {
            pa.src[i] = srcs[i];
            pa.dst[i] = dsts[i];
            pa.start[i] = s;
            s += (int)(n4s[i] / 256);
        }
        pa.start[9] = s;
        k_prep<<<s, 256>>>(pa);
    }
    // 2. slot alignment (profile slot 3 = GEMM1)
    k_nop<<<1, 32>>>();
    // 3. merged GEMM #1 — split-K conv1 (2x64-chunk halves), LPT order
    {
        GemmP g;
        int s = 0;
        const __half* keyB = hh + H_KEYR + (size_t)2 * Ww * Dm;
        const __half* valB = hh + H_VALR + (size_t)2 * Ww * Dm;
        s = add_seg(g, 0, s, hh + H_KEYR, hh + H_W11T,        ff + S_C1K,  nullptr, nullptr, 1.f, M1, 512, 4096, 1, 0, K1);
        s = add_seg(g, 1, s, keyB,        hh + H_W11T + 4096, ff + S_C1KB, nullptr, nullptr, 1.f, M1, 512, 4096, 1, 0, K1);
        s = add_seg(g, 2, s, hh + H_VALR, hh + H_W12T,        ff + S_C1V,  nullptr, nullptr, 1.f, M1, 512, 4096, 1, 0, K1);
        s = add_seg(g, 3, s, valB,        hh + H_W12T + 4096, ff + S_C1VB, nullptr, nullptr, 1.f, M1, 512, 4096, 1, 0, K1);
        s = add_seg(g, 4, s, hh + H_KEYR, hh + H_W21T, ff + S_C2K, nullptr, nullptr, 1.f, M2, 512, K2, 2);
        s = add_seg(g, 5, s, hh + H_VALR, hh + H_W22T, ff + S_C2V, nullptr, nullptr, 1.f, M2, 512, K2, 2);
        s = add_seg(g, 6, s, hh + H_QR,   hh + H_QWR,  nullptr, hh + H_PQ, nullptr, 0.125f, MQ, 512, 512, 0);
        g.nseg = 7;
        k_gemm<<<s, 256, GSMEM_BYTES>>>(g);
    }
    // 4. LN -> fp16 (branch1 sums split-K halves)
    {
        LnP p;
        p.x[0] = ff + S_C1K; p.x2[0] = ff + S_C1KB; p.cb[0] = sr11b; p.g[0] = n11g; p.b[0] = n11b; p.o[0] = hh + H_LN1K;
        p.x[1] = ff + S_C1V; p.x2[1] = ff + S_C1VB; p.cb[1] = sr12b; p.g[1] = n12g; p.b[1] = n12b; p.o[1] = hh + H_LN1V;
        p.x[2] = ff + S_C2K; p.x2[2] = nullptr;     p.cb[2] = sr21b; p.g[2] = n21g; p.b[2] = n21b; p.o[2] = hh + H_LN2K;
        p.x[3] = ff + S_C2V; p.x2[3] = nullptr;     p.cb[3] = sr22b; p.g[3] = n22g; p.b[3] = n22b; p.o[3] = hh + H_LN2V;
        k_biasln<<<(LNROWS + 7) / 8, 256>>>(p);
    }
    // 5. merged GEMM #2
    {
        GemmP g;
        int s = 0;
        s = add_seg(g, 0, s, hh + H_LN2K, hh + H_KW2R, nullptr, hh + H_KB2, nullptr, 1.f, M2, 256, 512, 0);
        s = add_seg(g, 1, s, hh + H_LN2V, hh + H_VW2R, ff + S_VB2, nullptr, nullptr, 1.f, M2, 256, 512, 0);
        s = add_seg(g, 2, s, hh + H_LN1K, hh + H_KW1R, nullptr, hh + H_KB1, nullptr, 1.f, M1, 256, 512, 0);
        s = add_seg(g, 3, s, hh + H_LN1V, hh + H_VW1R, ff + S_VB1, nullptr, nullptr, 1.f, M1, 256, 512, 0);
        g.nseg = 4;
        k_gemm<<<s, 256, GSMEM_BYTES>>>(g);
    }
    // 6. depthwise local V + residual -> fp16
    {
        DwP p;
        p.v[0] = ff + S_VB1; p.vs[0] = hh + H_VS1; p.lw[0] = lc1w; p.lb[0] = lc1b;
        p.v[1] = ff + S_VB2; p.vs[1] = hh + H_VS2; p.lw[1] = lc2w; p.lb[1] = lc2b;
        k_dwadd<<<grd((long long)(M1 + M2) * 128), 256>>>(p);
    }
    // 7. attention scores (flattened 640-block grid)
    {
        AttnSP p;
        p.Qh = hh + H_PQ;
        p.Kh[0] = hh + H_KB1; p.Kh[1] = hh + H_KB2;
        p.S[0] = ff + S_S1;   p.S[1] = ff + S_S2;
        k_attn_s<<<640, 256, ASMEM_BYTES>>>(p);
    }
    // 8. softmax
    {
        SmP p;
        p.S[0] = ff + S_S1; p.S[1] = ff + S_S2;
        p.P[0] = hh + H_P1; p.P[1] = hh + H_P2;
        p.inv[0] = ff + S_INV1; p.inv[1] = ff + S_INV2;
        k_softmax<<<(2 * ROWS1) / 8, 256>>>(p);
    }
    // 9. attention output (V direct from VS via ldmatrix.trans)
    {
        AttnOP p;
        p.P[0] = hh + H_P1; p.P[1] = hh + H_P2;
        p.VS[0] = hh + H_VS1; p.VS[1] = hh + H_VS2;
        p.inv[0] = ff + S_INV1; p.inv[1] = ff + S_INV2;
        p.xbuf = hh + H_X;
        k_attn_o<<<dim3(2, 8, 8), 256, GSMEM_BYTES>>>(p);
    }
    // 10. final projection (+bias)
    {
        GemmP g;
        int s = add_seg(g, 0, 0, hh + H_X, hh + H_PWR, out, nullptr, projb, 1.f, MQ, 512, 512, 0);
        g.nseg = 1;
        k_gemm<<<s, 256, GSMEM_BYTES>>>(g);
    }

    (void)in_sizes; (void)n_in; (void)out_size;
}